// round 1
// baseline (speedup 1.0000x reference)
#include <cuda_runtime.h>
#include <cuda_bf16.h>
#include <math.h>

#define NN 8192
#define ROWS 16
#define THREADS 512
#define NBLK (NN / ROWS)          // 512 main-kernel blocks
#define TILE 4096                 // columns per smem tile
#define TILE4 (TILE / 4)          // 1024 float4 per tile
#define PREP_BLOCKS (NN / THREADS) // 16

// Device scratch (allocation-free rule: __device__ globals)
__device__ __align__(16) float g_wsin[NN];
__device__ __align__(16) float g_wcos[NN];
__device__ float g_rc[PREP_BLOCKS];
__device__ float g_rs[PREP_BLOCKS];
__device__ float g_ksq[NBLK];
__device__ float g_kabs[NBLK];

// -------------------- prep: weights + R partials --------------------
__global__ __launch_bounds__(THREADS) void prep_kernel(
    const float* __restrict__ phases, const float* __restrict__ alive) {
    __shared__ float sc[16], ss[16];
    int i = blockIdx.x * THREADS + threadIdx.x;
    float s, c;
    sincosf(phases[i], &s, &c);
    float a = alive[i];
    g_wsin[i] = a * s;
    g_wcos[i] = a * c;

    // block-reduce raw cos/sin (for R)
    float vc = c, vs = s;
#pragma unroll
    for (int o = 16; o > 0; o >>= 1) {
        vc += __shfl_down_sync(0xffffffffu, vc, o);
        vs += __shfl_down_sync(0xffffffffu, vs, o);
    }
    int warp = threadIdx.x >> 5, lane = threadIdx.x & 31;
    if (lane == 0) { sc[warp] = vc; ss[warp] = vs; }
    __syncthreads();
    if (warp == 0) {
        vc = (lane < 16) ? sc[lane] : 0.f;
        vs = (lane < 16) ? ss[lane] : 0.f;
#pragma unroll
        for (int o = 8; o > 0; o >>= 1) {
            vc += __shfl_down_sync(0xffffffffu, vc, o);
            vs += __shfl_down_sync(0xffffffffu, vs, o);
        }
        if (lane == 0) { g_rc[blockIdx.x] = vc; g_rs[blockIdx.x] = vs; }
    }
}

// -------------------- main: fused row dots + K reductions --------------------
__global__ __launch_bounds__(THREADS) void main_kernel(
    const float* __restrict__ phases, const float* __restrict__ alive,
    const float4* __restrict__ D4, const float4* __restrict__ K4,
    float* __restrict__ out) {
    __shared__ float4 s_ws[TILE4];     // 16 KB
    __shared__ float4 s_wc[TILE4];     // 16 KB
    __shared__ float2 s_part[ROWS * 16]; // per-row, per-warp partials (2 KB)
    __shared__ float s_red[16];

    const int tid = threadIdx.x;
    const int warp = tid >> 5, lane = tid & 31;
    const int row0 = blockIdx.x * ROWS;

    float2 acc[ROWS];
#pragma unroll
    for (int r = 0; r < ROWS; ++r) acc[r] = make_float2(0.f, 0.f);
    float ksq = 0.f, kabs = 0.f;

    const float4* ws4g = reinterpret_cast<const float4*>(g_wsin);
    const float4* wc4g = reinterpret_cast<const float4*>(g_wcos);

#pragma unroll
    for (int ct = 0; ct < NN / TILE; ++ct) {
        __syncthreads();
        const float4* ws = ws4g + ct * TILE4;
        const float4* wc = wc4g + ct * TILE4;
        s_ws[tid]           = ws[tid];
        s_ws[tid + THREADS] = ws[tid + THREADS];
        s_wc[tid]           = wc[tid];
        s_wc[tid + THREADS] = wc[tid + THREADS];
        __syncthreads();

#pragma unroll
        for (int r = 0; r < ROWS; ++r) {
            const size_t rowoff = (size_t)(row0 + r) * (NN / 4) + (size_t)ct * TILE4;
            const float4* Kr = K4 + rowoff;
            const float4* Dr = D4 + rowoff;
#pragma unroll
            for (int it = 0; it < TILE4 / THREADS; ++it) {
                const int idx = it * THREADS + tid;
                float4 k = Kr[idx];
                float4 d = Dr[idx];
                float4 w1 = s_ws[idx];
                float4 w2 = s_wc[idx];
                float m0 = k.x * d.x, m1 = k.y * d.y, m2 = k.z * d.z, m3 = k.w * d.w;
                float ax = acc[r].x, ay = acc[r].y;
                ax = fmaf(m0, w1.x, ax); ay = fmaf(m0, w2.x, ay);
                ax = fmaf(m1, w1.y, ax); ay = fmaf(m1, w2.y, ay);
                ax = fmaf(m2, w1.z, ax); ay = fmaf(m2, w2.z, ay);
                ax = fmaf(m3, w1.w, ax); ay = fmaf(m3, w2.w, ay);
                acc[r].x = ax; acc[r].y = ay;
                ksq = fmaf(k.x, k.x, ksq); ksq = fmaf(k.y, k.y, ksq);
                ksq = fmaf(k.z, k.z, ksq); ksq = fmaf(k.w, k.w, ksq);
                kabs += fabsf(k.x) + fabsf(k.y) + fabsf(k.z) + fabsf(k.w);
            }
        }
    }

    // per-row reductions across the block (deterministic, no atomics)
#pragma unroll
    for (int r = 0; r < ROWS; ++r) {
        float2 v = acc[r];
#pragma unroll
        for (int o = 16; o > 0; o >>= 1) {
            v.x += __shfl_down_sync(0xffffffffu, v.x, o);
            v.y += __shfl_down_sync(0xffffffffu, v.y, o);
        }
        if (lane == 0) s_part[r * 16 + warp] = v;
    }
    __syncthreads();

    if (tid < ROWS) {
        const int r = tid;
        float sx = 0.f, sy = 0.f;
#pragma unroll
        for (int w = 0; w < 16; ++w) { sx += s_part[r * 16 + w].x; sy += s_part[r * 16 + w].y; }
        const int row = row0 + r;
        float sp, cp;
        sincosf(phases[row], &sp, &cp);
        const float a = alive[row];
        out[1 + row] = a * (cp * sx - sp * sy);   // dtheta[row]
    }

    // block reduce ksq / kabs
#pragma unroll
    for (int o = 16; o > 0; o >>= 1) {
        ksq  += __shfl_down_sync(0xffffffffu, ksq, o);
        kabs += __shfl_down_sync(0xffffffffu, kabs, o);
    }
    if (lane == 0) s_red[warp] = ksq;
    __syncthreads();
    if (warp == 0) {
        float v = (lane < 16) ? s_red[lane] : 0.f;
#pragma unroll
        for (int o = 8; o > 0; o >>= 1) v += __shfl_down_sync(0xffffffffu, v, o);
        if (lane == 0) g_ksq[blockIdx.x] = v;
    }
    __syncthreads();
    if (lane == 0) s_red[warp] = kabs;
    __syncthreads();
    if (warp == 0) {
        float v = (lane < 16) ? s_red[lane] : 0.f;
#pragma unroll
        for (int o = 8; o > 0; o >>= 1) v += __shfl_down_sync(0xffffffffu, v, o);
        if (lane == 0) g_kabs[blockIdx.x] = v;
    }
}

// -------------------- finalize: R and loss --------------------
__global__ __launch_bounds__(THREADS) void final_kernel(float* __restrict__ out) {
    __shared__ float s1[16], s2[16];
    const int tid = threadIdx.x;
    const int warp = tid >> 5, lane = tid & 31;

    float ksq = g_ksq[tid];   // NBLK == THREADS == 512
    float kabs = g_kabs[tid];
#pragma unroll
    for (int o = 16; o > 0; o >>= 1) {
        ksq  += __shfl_down_sync(0xffffffffu, ksq, o);
        kabs += __shfl_down_sync(0xffffffffu, kabs, o);
    }
    if (lane == 0) { s1[warp] = ksq; s2[warp] = kabs; }
    __syncthreads();
    if (tid == 0) {
        float tksq = 0.f, tkabs = 0.f;
#pragma unroll
        for (int w = 0; w < 16; ++w) { tksq += s1[w]; tkabs += s2[w]; }
        float rc = 0.f, rs = 0.f;
#pragma unroll
        for (int i = 0; i < PREP_BLOCKS; ++i) { rc += g_rc[i]; rs += g_rs[i]; }
        const float mc = rc / (float)NN;
        const float ms = rs / (float)NN;
        const float R = sqrtf(mc * mc + ms * ms);
        out[0] = R;
        out[NN + 1] = 1.0f - R + 0.01f * sqrtf(tksq) + 0.01f * tkabs;
    }
}

extern "C" void kernel_launch(void* const* d_in, const int* in_sizes, int n_in,
                              void* d_out, int out_size) {
    const float* phases = (const float*)d_in[0];
    const float* alive  = (const float*)d_in[1];
    const float4* dist4 = (const float4*)d_in[2];
    const float4* K4    = (const float4*)d_in[3];
    float* out = (float*)d_out;

    prep_kernel<<<PREP_BLOCKS, THREADS>>>(phases, alive);
    main_kernel<<<NBLK, THREADS>>>(phases, alive, dist4, K4, out);
    final_kernel<<<1, THREADS>>>(out);
}

// round 2
// speedup vs baseline: 1.0639x; 1.0639x over previous
#include <cuda_runtime.h>
#include <cuda_bf16.h>
#include <math.h>

#define NN 8192
#define N4 (NN / 4)               // 2048 float4 per row
#define ROWS 8
#define THREADS 512
#define NBLK (NN / ROWS)          // 1024 main-kernel blocks
#define PREP_BLOCKS 32
#define PREP_THREADS 256

// Device scratch (allocation-free rule: __device__ globals)
__device__ __align__(16) float g_wsin[NN];
__device__ __align__(16) float g_wcos[NN];
__device__ float g_rc[PREP_BLOCKS];
__device__ float g_rs[PREP_BLOCKS];
__device__ float g_ksq[NBLK];
__device__ float g_kabs[NBLK];

// -------------------- prep: weights + R partials --------------------
__global__ __launch_bounds__(PREP_THREADS) void prep_kernel(
    const float* __restrict__ phases, const float* __restrict__ alive) {
    __shared__ float sc[8], ss[8];
    int i = blockIdx.x * PREP_THREADS + threadIdx.x;
    float s, c;
    sincosf(phases[i], &s, &c);
    float a = alive[i];
    g_wsin[i] = a * s;
    g_wcos[i] = a * c;

    // block-reduce raw cos/sin (for R)
    float vc = c, vs = s;
#pragma unroll
    for (int o = 16; o > 0; o >>= 1) {
        vc += __shfl_down_sync(0xffffffffu, vc, o);
        vs += __shfl_down_sync(0xffffffffu, vs, o);
    }
    int warp = threadIdx.x >> 5, lane = threadIdx.x & 31;
    if (lane == 0) { sc[warp] = vc; ss[warp] = vs; }
    __syncthreads();
    if (warp == 0) {
        vc = (lane < 8) ? sc[lane] : 0.f;
        vs = (lane < 8) ? ss[lane] : 0.f;
#pragma unroll
        for (int o = 4; o > 0; o >>= 1) {
            vc += __shfl_down_sync(0xffffffffu, vc, o);
            vs += __shfl_down_sync(0xffffffffu, vs, o);
        }
        if (lane == 0) { g_rc[blockIdx.x] = vc; g_rs[blockIdx.x] = vs; }
    }
}

// -------------------- main: fused row dots + K reductions --------------------
__global__ __launch_bounds__(THREADS, 2) void main_kernel(
    const float* __restrict__ phases, const float* __restrict__ alive,
    const float4* __restrict__ D4, const float4* __restrict__ K4,
    float* __restrict__ out) {
    __shared__ float4 s_ws[N4];          // 32 KB
    __shared__ float4 s_wc[N4];          // 32 KB
    __shared__ float2 s_part[ROWS * 16]; // per-row, per-warp partials
    __shared__ float s_red[16];

    const int tid = threadIdx.x;
    const int warp = tid >> 5, lane = tid & 31;
    const int row0 = blockIdx.x * ROWS;

    // Stage full weight vectors once (L2-resident source, 4 float4 per thread)
    const float4* ws4g = reinterpret_cast<const float4*>(g_wsin);
    const float4* wc4g = reinterpret_cast<const float4*>(g_wcos);
#pragma unroll
    for (int j = 0; j < N4 / THREADS; ++j) {
        s_ws[j * THREADS + tid] = ws4g[j * THREADS + tid];
        s_wc[j * THREADS + tid] = wc4g[j * THREADS + tid];
    }
    __syncthreads();

    float2 acc[ROWS];
#pragma unroll
    for (int r = 0; r < ROWS; ++r) acc[r] = make_float2(0.f, 0.f);
    float ksq = 0.f, kabs = 0.f;

#pragma unroll
    for (int r = 0; r < ROWS; ++r) {
        const size_t rowoff = (size_t)(row0 + r) * N4;
        const float4* Kr = K4 + rowoff;
        const float4* Dr = D4 + rowoff;
#pragma unroll
        for (int it = 0; it < N4 / THREADS; ++it) {
            const int idx = it * THREADS + tid;
            float4 k = __ldcs(&Kr[idx]);
            float4 d = __ldcs(&Dr[idx]);
            float4 w1 = s_ws[idx];
            float4 w2 = s_wc[idx];
            float m0 = k.x * d.x, m1 = k.y * d.y, m2 = k.z * d.z, m3 = k.w * d.w;
            float ax = acc[r].x, ay = acc[r].y;
            ax = fmaf(m0, w1.x, ax); ay = fmaf(m0, w2.x, ay);
            ax = fmaf(m1, w1.y, ax); ay = fmaf(m1, w2.y, ay);
            ax = fmaf(m2, w1.z, ax); ay = fmaf(m2, w2.z, ay);
            ax = fmaf(m3, w1.w, ax); ay = fmaf(m3, w2.w, ay);
            acc[r].x = ax; acc[r].y = ay;
            ksq = fmaf(k.x, k.x, ksq); ksq = fmaf(k.y, k.y, ksq);
            ksq = fmaf(k.z, k.z, ksq); ksq = fmaf(k.w, k.w, ksq);
            kabs += fabsf(k.x) + fabsf(k.y) + fabsf(k.z) + fabsf(k.w);
        }
    }

    // per-row reductions across the block (deterministic, no atomics)
#pragma unroll
    for (int r = 0; r < ROWS; ++r) {
        float2 v = acc[r];
#pragma unroll
        for (int o = 16; o > 0; o >>= 1) {
            v.x += __shfl_down_sync(0xffffffffu, v.x, o);
            v.y += __shfl_down_sync(0xffffffffu, v.y, o);
        }
        if (lane == 0) s_part[r * 16 + warp] = v;
    }
    __syncthreads();

    if (tid < ROWS) {
        const int r = tid;
        float sx = 0.f, sy = 0.f;
#pragma unroll
        for (int w = 0; w < 16; ++w) { sx += s_part[r * 16 + w].x; sy += s_part[r * 16 + w].y; }
        const int row = row0 + r;
        float sp, cp;
        sincosf(phases[row], &sp, &cp);
        const float a = alive[row];
        out[1 + row] = a * (cp * sx - sp * sy);   // dtheta[row]
    }

    // block reduce ksq / kabs
#pragma unroll
    for (int o = 16; o > 0; o >>= 1) {
        ksq  += __shfl_down_sync(0xffffffffu, ksq, o);
        kabs += __shfl_down_sync(0xffffffffu, kabs, o);
    }
    if (lane == 0) s_red[warp] = ksq;
    __syncthreads();
    if (warp == 0) {
        float v = (lane < 16) ? s_red[lane] : 0.f;
#pragma unroll
        for (int o = 8; o > 0; o >>= 1) v += __shfl_down_sync(0xffffffffu, v, o);
        if (lane == 0) g_ksq[blockIdx.x] = v;
    }
    __syncthreads();
    if (lane == 0) s_red[warp] = kabs;
    __syncthreads();
    if (warp == 0) {
        float v = (lane < 16) ? s_red[lane] : 0.f;
#pragma unroll
        for (int o = 8; o > 0; o >>= 1) v += __shfl_down_sync(0xffffffffu, v, o);
        if (lane == 0) g_kabs[blockIdx.x] = v;
    }
}

// -------------------- finalize: R and loss --------------------
__global__ __launch_bounds__(THREADS) void final_kernel(float* __restrict__ out) {
    __shared__ float s1[16], s2[16];
    const int tid = threadIdx.x;
    const int warp = tid >> 5, lane = tid & 31;

    float ksq  = g_ksq[tid]  + g_ksq[tid + THREADS];    // NBLK == 2*THREADS
    float kabs = g_kabs[tid] + g_kabs[tid + THREADS];
#pragma unroll
    for (int o = 16; o > 0; o >>= 1) {
        ksq  += __shfl_down_sync(0xffffffffu, ksq, o);
        kabs += __shfl_down_sync(0xffffffffu, kabs, o);
    }
    if (lane == 0) { s1[warp] = ksq; s2[warp] = kabs; }
    __syncthreads();
    if (tid == 0) {
        float tksq = 0.f, tkabs = 0.f;
#pragma unroll
        for (int w = 0; w < 16; ++w) { tksq += s1[w]; tkabs += s2[w]; }
        float rc = 0.f, rs = 0.f;
#pragma unroll
        for (int i = 0; i < PREP_BLOCKS; ++i) { rc += g_rc[i]; rs += g_rs[i]; }
        const float mc = rc / (float)NN;
        const float ms = rs / (float)NN;
        const float R = sqrtf(mc * mc + ms * ms);
        out[0] = R;
        out[NN + 1] = 1.0f - R + 0.01f * sqrtf(tksq) + 0.01f * tkabs;
    }
}

extern "C" void kernel_launch(void* const* d_in, const int* in_sizes, int n_in,
                              void* d_out, int out_size) {
    const float* phases = (const float*)d_in[0];
    const float* alive  = (const float*)d_in[1];
    const float4* dist4 = (const float4*)d_in[2];
    const float4* K4    = (const float4*)d_in[3];
    float* out = (float*)d_out;

    prep_kernel<<<PREP_BLOCKS, PREP_THREADS>>>(phases, alive);
    main_kernel<<<NBLK, THREADS>>>(phases, alive, dist4, K4, out);
    final_kernel<<<1, THREADS>>>(out);
}

// round 3
// speedup vs baseline: 1.1242x; 1.0566x over previous
#include <cuda_runtime.h>
#include <cuda_bf16.h>
#include <math.h>

#define NN 8192
#define N4 (NN / 4)               // 2048 float4 per row
#define BATCH 4                   // rows per group
#define NGROUPS (NN / BATCH)      // 2048 row-groups
#define THREADS 512
#define GRID 304                  // 2 blocks per SM on 152 SMs, persistent
#define FIN_THREADS 512

// Device scratch (allocation-free rule: __device__ globals)
__device__ float g_ksq[GRID];
__device__ float g_kabs[GRID];

// -------------------- main: persistent, fused weights + row dots + K reductions --------------------
__global__ __launch_bounds__(THREADS, 2) void main_kernel(
    const float* __restrict__ phases, const float* __restrict__ alive,
    const float4* __restrict__ D4, const float4* __restrict__ K4,
    float* __restrict__ out) {
    __shared__ float4 s_ws[N4];               // 32 KB  (alive*sin)
    __shared__ float4 s_wc[N4];               // 32 KB  (alive*cos)
    __shared__ float2 s_part[2][BATCH * 16];  // double-buffered per-group partials
    __shared__ float s_red[16];

    const int tid = threadIdx.x;
    const int warp = tid >> 5, lane = tid & 31;

    // Stage weights: compute sincos directly from inputs (fused prep)
    {
        float* ws = reinterpret_cast<float*>(s_ws);
        float* wc = reinterpret_cast<float*>(s_wc);
#pragma unroll
        for (int j = 0; j < NN / THREADS; ++j) {
            const int i = j * THREADS + tid;
            float s, c;
            sincosf(phases[i], &s, &c);
            const float a = alive[i];
            ws[i] = a * s;
            wc[i] = a * c;
        }
    }
    __syncthreads();

    float ksq = 0.f, kabs = 0.f;
    int parity = 0;

    for (int g = blockIdx.x; g < NGROUPS; g += GRID) {
        const int row0 = g * BATCH;
        float2 acc[BATCH];
#pragma unroll
        for (int r = 0; r < BATCH; ++r) acc[r] = make_float2(0.f, 0.f);

#pragma unroll
        for (int r = 0; r < BATCH; ++r) {
            const size_t rowoff = (size_t)(row0 + r) * N4;
            const float4* Kr = K4 + rowoff;
            const float4* Dr = D4 + rowoff;
#pragma unroll
            for (int it = 0; it < N4 / THREADS; ++it) {
                const int idx = it * THREADS + tid;
                float4 k = __ldcs(&Kr[idx]);
                float4 d = __ldcs(&Dr[idx]);
                float4 w1 = s_ws[idx];
                float4 w2 = s_wc[idx];
                float m0 = k.x * d.x, m1 = k.y * d.y, m2 = k.z * d.z, m3 = k.w * d.w;
                float ax = acc[r].x, ay = acc[r].y;
                ax = fmaf(m0, w1.x, ax); ay = fmaf(m0, w2.x, ay);
                ax = fmaf(m1, w1.y, ax); ay = fmaf(m1, w2.y, ay);
                ax = fmaf(m2, w1.z, ax); ay = fmaf(m2, w2.z, ay);
                ax = fmaf(m3, w1.w, ax); ay = fmaf(m3, w2.w, ay);
                acc[r].x = ax; acc[r].y = ay;
                ksq = fmaf(k.x, k.x, ksq); ksq = fmaf(k.y, k.y, ksq);
                ksq = fmaf(k.z, k.z, ksq); ksq = fmaf(k.w, k.w, ksq);
                kabs += fabsf(k.x) + fabsf(k.y) + fabsf(k.z) + fabsf(k.w);
            }
        }

        // per-row reductions (deterministic)
#pragma unroll
        for (int r = 0; r < BATCH; ++r) {
            float2 v = acc[r];
#pragma unroll
            for (int o = 16; o > 0; o >>= 1) {
                v.x += __shfl_down_sync(0xffffffffu, v.x, o);
                v.y += __shfl_down_sync(0xffffffffu, v.y, o);
            }
            if (lane == 0) s_part[parity][r * 16 + warp] = v;
        }
        __syncthreads();

        if (tid < BATCH) {
            float sx = 0.f, sy = 0.f;
#pragma unroll
            for (int w = 0; w < 16; ++w) {
                sx += s_part[parity][tid * 16 + w].x;
                sy += s_part[parity][tid * 16 + w].y;
            }
            const int row = row0 + tid;
            float sp, cp;
            sincosf(phases[row], &sp, &cp);
            out[1 + row] = alive[row] * (cp * sx - sp * sy);   // dtheta[row]
        }
        parity ^= 1;
    }

    // block reduce ksq / kabs → per-block partials
#pragma unroll
    for (int o = 16; o > 0; o >>= 1) {
        ksq  += __shfl_down_sync(0xffffffffu, ksq, o);
        kabs += __shfl_down_sync(0xffffffffu, kabs, o);
    }
    if (lane == 0) s_red[warp] = ksq;
    __syncthreads();
    if (warp == 0) {
        float v = (lane < 16) ? s_red[lane] : 0.f;
#pragma unroll
        for (int o = 8; o > 0; o >>= 1) v += __shfl_down_sync(0xffffffffu, v, o);
        if (lane == 0) g_ksq[blockIdx.x] = v;
    }
    __syncthreads();
    if (lane == 0) s_red[warp] = kabs;
    __syncthreads();
    if (warp == 0) {
        float v = (lane < 16) ? s_red[lane] : 0.f;
#pragma unroll
        for (int o = 8; o > 0; o >>= 1) v += __shfl_down_sync(0xffffffffu, v, o);
        if (lane == 0) g_kabs[blockIdx.x] = v;
    }
}

// -------------------- finalize: R (recomputed) and loss --------------------
__global__ __launch_bounds__(FIN_THREADS) void final_kernel(
    const float* __restrict__ phases, float* __restrict__ out) {
    __shared__ float s1[16], s2[16], s3[16], s4[16];
    const int tid = threadIdx.x;
    const int warp = tid >> 5, lane = tid & 31;

    // R partial sums: each thread handles 16 phases
    float vc = 0.f, vs = 0.f;
#pragma unroll
    for (int j = 0; j < NN / FIN_THREADS; ++j) {
        float s, c;
        sincosf(phases[j * FIN_THREADS + tid], &s, &c);
        vc += c; vs += s;
    }
    // K partial sums: GRID=304 entries
    float ksq = (tid < GRID) ? g_ksq[tid] : 0.f;
    float kabs = (tid < GRID) ? g_kabs[tid] : 0.f;

#pragma unroll
    for (int o = 16; o > 0; o >>= 1) {
        vc   += __shfl_down_sync(0xffffffffu, vc, o);
        vs   += __shfl_down_sync(0xffffffffu, vs, o);
        ksq  += __shfl_down_sync(0xffffffffu, ksq, o);
        kabs += __shfl_down_sync(0xffffffffu, kabs, o);
    }
    if (lane == 0) { s1[warp] = vc; s2[warp] = vs; s3[warp] = ksq; s4[warp] = kabs; }
    __syncthreads();
    if (tid == 0) {
        float tc = 0.f, ts = 0.f, tksq = 0.f, tkabs = 0.f;
#pragma unroll
        for (int w = 0; w < 16; ++w) { tc += s1[w]; ts += s2[w]; tksq += s3[w]; tkabs += s4[w]; }
        const float mc = tc / (float)NN;
        const float ms = ts / (float)NN;
        const float R = sqrtf(mc * mc + ms * ms);
        out[0] = R;
        out[NN + 1] = 1.0f - R + 0.01f * sqrtf(tksq) + 0.01f * tkabs;
    }
}

extern "C" void kernel_launch(void* const* d_in, const int* in_sizes, int n_in,
                              void* d_out, int out_size) {
    const float* phases = (const float*)d_in[0];
    const float* alive  = (const float*)d_in[1];
    const float4* dist4 = (const float4*)d_in[2];
    const float4* K4    = (const float4*)d_in[3];
    float* out = (float*)d_out;

    main_kernel<<<GRID, THREADS>>>(phases, alive, dist4, K4, out);
    final_kernel<<<1, FIN_THREADS>>>(phases, out);
}

// round 4
// speedup vs baseline: 1.1431x; 1.0168x over previous
#include <cuda_runtime.h>
#include <cuda_bf16.h>
#include <math.h>

#define NN 8192
#define N4 (NN / 4)               // 2048 float4 per row
#define BATCH 4                   // rows per group
#define NGROUPS (NN / BATCH)      // 2048 row-groups
#define THREADS 512
#define GRID 304                  // 2 blocks per SM on 152 SMs, persistent

// Device scratch (allocation-free rule: __device__ globals)
__device__ float g_ksq[GRID];
__device__ float g_kabs[GRID];
__device__ float g_rc;            // sum cos(phases)
__device__ float g_rs;            // sum sin(phases)
__device__ unsigned g_count = 0;  // completion counter (self-resetting)

__global__ __launch_bounds__(THREADS, 2) void main_kernel(
    const float* __restrict__ phases, const float* __restrict__ alive,
    const float4* __restrict__ D4, const float4* __restrict__ K4,
    float* __restrict__ out) {
    __shared__ float4 s_ws[N4];               // 32 KB  (alive*sin)
    __shared__ float4 s_wc[N4];               // 32 KB  (alive*cos)
    __shared__ float2 s_part[2][BATCH * 16];  // double-buffered per-group partials
    __shared__ float s_red[16];
    __shared__ float s_red2[16];
    __shared__ unsigned s_last;

    const int tid = threadIdx.x;
    const int warp = tid >> 5, lane = tid & 31;

    // ---- Stage weights (fused prep); block 0 also reduces raw sin/cos for R ----
    {
        float* ws = reinterpret_cast<float*>(s_ws);
        float* wc = reinterpret_cast<float*>(s_wc);
        float vc = 0.f, vs = 0.f;
#pragma unroll
        for (int j = 0; j < NN / THREADS; ++j) {
            const int i = j * THREADS + tid;
            float s, c;
            sincosf(phases[i], &s, &c);
            const float a = alive[i];
            ws[i] = a * s;
            wc[i] = a * c;
            vc += c; vs += s;
        }
        if (blockIdx.x == 0) {
#pragma unroll
            for (int o = 16; o > 0; o >>= 1) {
                vc += __shfl_down_sync(0xffffffffu, vc, o);
                vs += __shfl_down_sync(0xffffffffu, vs, o);
            }
            if (lane == 0) { s_red[warp] = vc; s_red2[warp] = vs; }
            __syncthreads();
            if (tid == 0) {
                float tc = 0.f, ts = 0.f;
#pragma unroll
                for (int w = 0; w < 16; ++w) { tc += s_red[w]; ts += s_red2[w]; }
                g_rc = tc; g_rs = ts;
            }
        }
    }
    __syncthreads();

    // ---- Main streaming loop ----
    float ksq = 0.f, kabs = 0.f;
    int parity = 0;

    for (int g = blockIdx.x; g < NGROUPS; g += GRID) {
        const int row0 = g * BATCH;
        float2 acc[BATCH];
#pragma unroll
        for (int r = 0; r < BATCH; ++r) acc[r] = make_float2(0.f, 0.f);

#pragma unroll
        for (int r = 0; r < BATCH; ++r) {
            const size_t rowoff = (size_t)(row0 + r) * N4;
            const float4* Kr = K4 + rowoff;
            const float4* Dr = D4 + rowoff;
#pragma unroll
            for (int it = 0; it < N4 / THREADS; ++it) {
                const int idx = it * THREADS + tid;
                float4 k = __ldcs(&Kr[idx]);
                float4 d = __ldcs(&Dr[idx]);
                float4 w1 = s_ws[idx];
                float4 w2 = s_wc[idx];
                float m0 = k.x * d.x, m1 = k.y * d.y, m2 = k.z * d.z, m3 = k.w * d.w;
                float ax = acc[r].x, ay = acc[r].y;
                ax = fmaf(m0, w1.x, ax); ay = fmaf(m0, w2.x, ay);
                ax = fmaf(m1, w1.y, ax); ay = fmaf(m1, w2.y, ay);
                ax = fmaf(m2, w1.z, ax); ay = fmaf(m2, w2.z, ay);
                ax = fmaf(m3, w1.w, ax); ay = fmaf(m3, w2.w, ay);
                acc[r].x = ax; acc[r].y = ay;
                ksq = fmaf(k.x, k.x, ksq); ksq = fmaf(k.y, k.y, ksq);
                ksq = fmaf(k.z, k.z, ksq); ksq = fmaf(k.w, k.w, ksq);
                kabs += fabsf(k.x) + fabsf(k.y) + fabsf(k.z) + fabsf(k.w);
            }
        }

        // per-row reductions (deterministic)
#pragma unroll
        for (int r = 0; r < BATCH; ++r) {
            float2 v = acc[r];
#pragma unroll
            for (int o = 16; o > 0; o >>= 1) {
                v.x += __shfl_down_sync(0xffffffffu, v.x, o);
                v.y += __shfl_down_sync(0xffffffffu, v.y, o);
            }
            if (lane == 0) s_part[parity][r * 16 + warp] = v;
        }
        __syncthreads();

        if (tid < BATCH) {
            float sx = 0.f, sy = 0.f;
#pragma unroll
            for (int w = 0; w < 16; ++w) {
                sx += s_part[parity][tid * 16 + w].x;
                sy += s_part[parity][tid * 16 + w].y;
            }
            const int row = row0 + tid;
            float sp, cp;
            sincosf(phases[row], &sp, &cp);
            out[1 + row] = alive[row] * (cp * sx - sp * sy);   // dtheta[row]
        }
        parity ^= 1;
    }

    // ---- Block-level ksq/kabs partials ----
#pragma unroll
    for (int o = 16; o > 0; o >>= 1) {
        ksq  += __shfl_down_sync(0xffffffffu, ksq, o);
        kabs += __shfl_down_sync(0xffffffffu, kabs, o);
    }
    if (lane == 0) { s_red[warp] = ksq; s_red2[warp] = kabs; }
    __syncthreads();
    if (tid == 0) {
        float v1 = 0.f, v2 = 0.f;
#pragma unroll
        for (int w = 0; w < 16; ++w) { v1 += s_red[w]; v2 += s_red2[w]; }
        g_ksq[blockIdx.x] = v1;
        g_kabs[blockIdx.x] = v2;
    }

    // ---- Fused finalize: last block computes R + loss ----
    __threadfence();
    __syncthreads();
    if (tid == 0) s_last = atomicAdd(&g_count, 1u);
    __syncthreads();
    if (s_last == GRID - 1) {
        float k1 = (tid < GRID) ? g_ksq[tid] : 0.f;
        float k2 = (tid < GRID) ? g_kabs[tid] : 0.f;
#pragma unroll
        for (int o = 16; o > 0; o >>= 1) {
            k1 += __shfl_down_sync(0xffffffffu, k1, o);
            k2 += __shfl_down_sync(0xffffffffu, k2, o);
        }
        if (lane == 0) { s_red[warp] = k1; s_red2[warp] = k2; }
        __syncthreads();
        if (tid == 0) {
            float tksq = 0.f, tkabs = 0.f;
#pragma unroll
            for (int w = 0; w < 16; ++w) { tksq += s_red[w]; tkabs += s_red2[w]; }
            const float mc = g_rc / (float)NN;
            const float ms = g_rs / (float)NN;
            const float R = sqrtf(mc * mc + ms * ms);
            out[0] = R;
            out[NN + 1] = 1.0f - R + 0.01f * sqrtf(tksq) + 0.01f * tkabs;
            g_count = 0;   // reset for next graph replay
        }
    }
}

extern "C" void kernel_launch(void* const* d_in, const int* in_sizes, int n_in,
                              void* d_out, int out_size) {
    const float* phases = (const float*)d_in[0];
    const float* alive  = (const float*)d_in[1];
    const float4* dist4 = (const float4*)d_in[2];
    const float4* K4    = (const float4*)d_in[3];
    float* out = (float*)d_out;

    main_kernel<<<GRID, THREADS>>>(phases, alive, dist4, K4, out);
}